// round 1
// baseline (speedup 1.0000x reference)
#include <cuda_runtime.h>
#include <cstdint>

// Problem constants (from reference): B=8192, T=2048, H=5, input dim 1.
#define MAX_B 8192
#define MAX_T 2048
#define HID 5
#define NG (4 * HID)  // 20 gates: rows 0..4=i, 5..9=f, 10..14=g(tanh), 15..19=o

// Transposed x: xT[t][b], fully coalesced recurrent loads.
__device__ float g_xT[(size_t)MAX_T * MAX_B];

__device__ __forceinline__ float fast_ex2(float x) {
    float r;
    asm("ex2.approx.f32 %0, %1;" : "=f"(r) : "f"(x));
    return r;
}
__device__ __forceinline__ float fast_rcp(float x) {
    float r;
    asm("rcp.approx.f32 %0, %1;" : "=f"(r) : "f"(x));
    return r;
}

// ---------------- transpose: x[B,T] -> xT[T,B] ----------------
__global__ void transpose_kernel(const float* __restrict__ x, int B, int T) {
    __shared__ float tile[32][33];
    int t0 = blockIdx.x * 32;
    int b0 = blockIdx.y * 32;
    // load x[b0+i][t0+tx] coalesced along t
    #pragma unroll
    for (int i = threadIdx.y; i < 32; i += 8) {
        tile[i][threadIdx.x] = x[(size_t)(b0 + i) * T + t0 + threadIdx.x];
    }
    __syncthreads();
    // store xT[t0+i][b0+tx] coalesced along b
    #pragma unroll
    for (int i = threadIdx.y; i < 32; i += 8) {
        g_xT[(size_t)(t0 + i) * B + b0 + threadIdx.x] = tile[threadIdx.x][i];
    }
}

// ---------------- LSTM recurrence: one thread per sequence ----------------
__global__ void __launch_bounds__(64, 1) lstm_kernel(
    const float* __restrict__ W_ih,   // [20,1]
    const float* __restrict__ W_hh,   // [20,5]
    const float* __restrict__ b_ih,   // [20]
    const float* __restrict__ b_hh,   // [20]
    const float* __restrict__ W_fc,   // [1,5]
    const float* __restrict__ b_fc,   // [1]
    float* __restrict__ out,          // [B,1]
    int B, int T)
{
    const int b = blockIdx.x * blockDim.x + threadIdx.x;
    if (b >= B) return;

    const float LOG2E = 1.4426950408889634f;

    // Prescaled weights:
    //   sigmoid gates (i,f,o): z' = -log2e * z  ->  sig = 1/(1+2^z')
    //   tanh gate (g):         z' = -2*log2e*z  ->  tanh = 2/(1+2^z') - 1
    float wih[NG], bias[NG], whh[NG][HID];
    #pragma unroll
    for (int g = 0; g < NG; g++) {
        const bool is_tanh = (g >= 10 && g < 15);
        const float s = is_tanh ? (-2.0f * LOG2E) : (-LOG2E);
        wih[g]  = W_ih[g] * s;
        bias[g] = (b_ih[g] + b_hh[g]) * s;
        #pragma unroll
        for (int j = 0; j < HID; j++) whh[g][j] = W_hh[g * HID + j] * s;
    }

    float h[HID], c[HID];
    #pragma unroll
    for (int j = 0; j < HID; j++) { h[j] = 0.0f; c[j] = 0.0f; }

    const float NEG2LOG2E = -2.0f * LOG2E;

    for (int t = 0; t < T; t++) {
        const float xv = g_xT[(size_t)t * B + b];

        float z[NG];
        #pragma unroll
        for (int g = 0; g < NG; g++) {
            float v = fmaf(xv, wih[g], bias[g]);
            #pragma unroll
            for (int j = 0; j < HID; j++) v = fmaf(h[j], whh[g][j], v);
            z[g] = v;
        }

        #pragma unroll
        for (int j = 0; j < HID; j++) {
            // sigmoid(i), sigmoid(f), tanh(g), sigmoid(o)
            const float ig = fast_rcp(1.0f + fast_ex2(z[j]));
            const float fg = fast_rcp(1.0f + fast_ex2(z[5 + j]));
            const float gg = fmaf(2.0f, fast_rcp(1.0f + fast_ex2(z[10 + j])), -1.0f);
            const float og = fast_rcp(1.0f + fast_ex2(z[15 + j]));

            c[j] = fmaf(fg, c[j], ig * gg);

            const float th = fmaf(2.0f, fast_rcp(1.0f + fast_ex2(c[j] * NEG2LOG2E)), -1.0f);
            h[j] = og * th;
        }
    }

    // relu(h) @ W_fc^T + b_fc
    float y = b_fc[0];
    #pragma unroll
    for (int j = 0; j < HID; j++) y = fmaf(fmaxf(h[j], 0.0f), W_fc[j], y);
    out[b] = y;
}

extern "C" void kernel_launch(void* const* d_in, const int* in_sizes, int n_in,
                              void* d_out, int out_size) {
    const float* x    = (const float*)d_in[0];
    const float* W_ih = (const float*)d_in[1];
    const float* W_hh = (const float*)d_in[2];
    const float* b_ih = (const float*)d_in[3];
    const float* b_hh = (const float*)d_in[4];
    const float* W_fc = (const float*)d_in[5];
    const float* b_fc = (const float*)d_in[6];
    float* out = (float*)d_out;

    const int B = out_size;              // 8192
    const int T = in_sizes[0] / B;       // 2048

    dim3 tthreads(32, 8);
    dim3 tgrid(T / 32, B / 32);
    transpose_kernel<<<tgrid, tthreads>>>(x, B, T);

    const int threads = 64;
    const int blocks = (B + threads - 1) / threads;  // 128 blocks -> 128 SMs x 2 SMSPs
    lstm_kernel<<<blocks, threads>>>(W_ih, W_hh, b_ih, b_hh, W_fc, b_fc, out, B, T);
}

// round 2
// speedup vs baseline: 3.5272x; 3.5272x over previous
#include <cuda_runtime.h>
#include <cstdint>

// Problem constants: B=8192, T=2048, H=5, input dim 1.
#define MAX_B 8192
#define MAX_T 2048
#define HID 5
#define NG (4 * HID)  // 20 gates: rows 0..4=i, 5..9=f, 10..14=g(tanh), 15..19=o

// Packed x: xP[t/8][b][8] -> per-thread float4 pair per 8 steps, coalesced.
__device__ float g_xP[(size_t)MAX_T * MAX_B];

__device__ __forceinline__ float fast_tanh(float x) {
    float r;
    asm("tanh.approx.f32 %0, %1;" : "=f"(r) : "f"(x));
    return r;
}

// ---------------- pack: x[B,T] -> xP[T/8][B][8] ----------------
__global__ void pack_kernel(const float* __restrict__ x, int B, int T) {
    const int nblk = T / 8;
    int idx = blockIdx.x * blockDim.x + threadIdx.x;   // over B * nblk
    if (idx >= B * nblk) return;
    int b = idx / nblk;
    int k = idx - b * nblk;
    // read 8 consecutive floats of x[b] (coalesced across threads, 2x ld.128)
    const float4* src = reinterpret_cast<const float4*>(x + (size_t)b * T + (size_t)k * 8);
    float4 u = src[0];
    float4 v = src[1];
    // write 32B contiguous (2x st.128) -> exact 32B sectors, no waste
    float4* dst = reinterpret_cast<float4*>(g_xP + ((size_t)k * B + b) * 8);
    dst[0] = u;
    dst[1] = v;
}

// ---------------- LSTM recurrence: one thread per sequence ----------------
__global__ void __launch_bounds__(64, 1) lstm_kernel(
    const float* __restrict__ W_ih,   // [20,1]
    const float* __restrict__ W_hh,   // [20,5]
    const float* __restrict__ b_ih,   // [20]
    const float* __restrict__ b_hh,   // [20]
    const float* __restrict__ W_fc,   // [1,5]
    const float* __restrict__ b_fc,   // [1]
    float* __restrict__ out,          // [B,1]
    int B, int T)
{
    const int b = blockIdx.x * blockDim.x + threadIdx.x;
    if (b >= B) return;

    // Prescale: sigmoid gates (i,f,o) use sig(z) = 0.5*tanh(z/2)+0.5,
    // so their weights/bias absorb the 1/2. tanh gate (g) unscaled.
    float wih[NG], bias[NG], whh[NG][HID];
    #pragma unroll
    for (int g = 0; g < NG; g++) {
        const bool is_tanh = (g >= 10 && g < 15);
        const float s = is_tanh ? 1.0f : 0.5f;
        wih[g]  = W_ih[g] * s;
        bias[g] = (b_ih[g] + b_hh[g]) * s;
        #pragma unroll
        for (int j = 0; j < HID; j++) whh[g][j] = W_hh[g * HID + j] * s;
    }

    float h[HID], c[HID];
    #pragma unroll
    for (int j = 0; j < HID; j++) { h[j] = 0.0f; c[j] = 0.0f; }

    const int nblk = T / 8;
    const float4* xp0 = reinterpret_cast<const float4*>(g_xP);

    // prime first block
    float4 u = xp0[((size_t)0 * B + b) * 2 + 0];
    float4 v = xp0[((size_t)0 * B + b) * 2 + 1];

    for (int tb = 0; tb < nblk; tb++) {
        // prefetch next block (clamped; hides DRAM latency under ~8 steps of compute)
        const int tn = (tb + 1 < nblk) ? (tb + 1) : tb;
        const float4 un = xp0[((size_t)tn * B + b) * 2 + 0];
        const float4 vn = xp0[((size_t)tn * B + b) * 2 + 1];

        const float xs[8] = {u.x, u.y, u.z, u.w, v.x, v.y, v.z, v.w};

        #pragma unroll
        for (int k = 0; k < 8; k++) {
            const float xv = xs[k];

            float z[NG];
            #pragma unroll
            for (int g = 0; g < NG; g++) {
                float vv = fmaf(xv, wih[g], bias[g]);
                #pragma unroll
                for (int j = 0; j < HID; j++) vv = fmaf(h[j], whh[g][j], vv);
                z[g] = vv;
            }

            #pragma unroll
            for (int j = 0; j < HID; j++) {
                const float ti = fast_tanh(z[j]);
                const float tf = fast_tanh(z[5 + j]);
                const float gg = fast_tanh(z[10 + j]);
                const float to = fast_tanh(z[15 + j]);

                const float ig = fmaf(0.5f, ti, 0.5f);
                const float fg = fmaf(0.5f, tf, 0.5f);
                const float og = fmaf(0.5f, to, 0.5f);

                c[j] = fmaf(fg, c[j], ig * gg);
                h[j] = og * fast_tanh(c[j]);
            }
        }

        u = un; v = vn;
    }

    // relu(h) @ W_fc^T + b_fc
    float y = b_fc[0];
    #pragma unroll
    for (int j = 0; j < HID; j++) y = fmaf(fmaxf(h[j], 0.0f), W_fc[j], y);
    out[b] = y;
}

extern "C" void kernel_launch(void* const* d_in, const int* in_sizes, int n_in,
                              void* d_out, int out_size) {
    const float* x    = (const float*)d_in[0];
    const float* W_ih = (const float*)d_in[1];
    const float* W_hh = (const float*)d_in[2];
    const float* b_ih = (const float*)d_in[3];
    const float* b_hh = (const float*)d_in[4];
    const float* W_fc = (const float*)d_in[5];
    const float* b_fc = (const float*)d_in[6];
    float* out = (float*)d_out;

    const int B = out_size;              // 8192
    const int T = in_sizes[0] / B;       // 2048

    const int npack = B * (T / 8);
    pack_kernel<<<(npack + 255) / 256, 256>>>(x, B, T);

    const int threads = 64;
    const int blocks = (B + threads - 1) / threads;  // 128 blocks -> 1 warp/SMSP on 128 SMs
    lstm_kernel<<<blocks, threads>>>(W_ih, W_hh, b_ih, b_hh, W_fc, b_fc, out, B, T);
}